// round 15
// baseline (speedup 1.0000x reference)
#include <cuda_runtime.h>
#include <cuda_fp16.h>
#include <math.h>

// Problem constants (fixed by the dataset)
constexpr int N_NODES = 50000;
constexpr int E_EDGES = 800000;
constexpr int DIN     = 128;      // also H*D_HEAD
constexpr int NHEAD   = 8;
constexpr int N_HALF  = 25000;    // dst-range split for scatter/gather pipeline
constexpr float INV_SCALE = 0.25f;   // 1/sqrt(16)

// Scratch (device globals — no allocation allowed).
__device__ __half g_hh[N_NODES * DIN];        // h in fp16
__device__ __half g_Wh[3 * DIN * DIN];        // Wq|Wk|Wv in fp16
__device__ __half g_Qh[N_NODES * DIN];
__device__ __half g_Kh[N_NODES * DIN];
__device__ __half g_Vh[N_NODES * DIN];
// CSR-by-dst structures
__device__ int g_deg[N_NODES];
__device__ int g_cur[N_NODES];
__device__ int g_off[N_NODES + 1];
__device__ int g_esrc[E_EDGES];

// ---------------------------------------------------------------------------
// Converters: fp32 -> fp16
// ---------------------------------------------------------------------------
__global__ void convert_h_kernel(const float* __restrict__ h)
{
    const int i = (blockIdx.x * blockDim.x + threadIdx.x) * 4;
    if (i >= N_NODES * DIN) return;
    float4 v = *reinterpret_cast<const float4*>(&h[i]);
    __half2 lo = __floats2half2_rn(v.x, v.y);
    __half2 hi = __floats2half2_rn(v.z, v.w);
    uint2 p;
    p.x = *reinterpret_cast<unsigned*>(&lo);
    p.y = *reinterpret_cast<unsigned*>(&hi);
    *reinterpret_cast<uint2*>(&g_hh[i]) = p;
}

__global__ void convert_w_kernel(const float* __restrict__ Wq,
                                 const float* __restrict__ Wk,
                                 const float* __restrict__ Wv)
{
    const int i = (blockIdx.x * blockDim.x + threadIdx.x) * 4;
    if (i >= 3 * DIN * DIN) return;
    const int mat = i >> 14;
    const int off = i & 16383;
    const float* W = (mat == 0) ? Wq : (mat == 1 ? Wk : Wv);
    float4 v = *reinterpret_cast<const float4*>(&W[off]);
    __half2 lo = __floats2half2_rn(v.x, v.y);
    __half2 hi = __floats2half2_rn(v.z, v.w);
    uint2 p;
    p.x = *reinterpret_cast<unsigned*>(&lo);
    p.y = *reinterpret_cast<unsigned*>(&hi);
    *reinterpret_cast<uint2*>(&g_Wh[i]) = p;
}

// ---------------------------------------------------------------------------
// CSR build (scalar hist/scatter; scatter split by dst range for pipelining)
// ---------------------------------------------------------------------------
__global__ void zero_deg_kernel()
{
    int i = blockIdx.x * blockDim.x + threadIdx.x;
    if (i < N_NODES) g_deg[i] = 0;
}

__global__ void hist_kernel(const int* __restrict__ dst)
{
    const int stride = gridDim.x * blockDim.x;
    for (int i = blockIdx.x * blockDim.x + threadIdx.x; i < E_EDGES; i += stride)
        atomicAdd(&g_deg[dst[i]], 1);
}

// Coalesced single-block scan; seeds g_cur = g_off.
__global__ __launch_bounds__(1024)
void scan_kernel()
{
    constexpr int WREG  = 1568;            // 49 * 32
    constexpr int ITERS = WREG / 32;       // 49
    __shared__ int warpTot[32];

    const int tid  = threadIdx.x;
    const int lane = tid & 31;
    const int w    = tid >> 5;
    const int base = w * WREG;

    int s = 0;
#pragma unroll
    for (int i = 0; i < ITERS; i++) {
        int idx = base + i * 32 + lane;
        if (idx < N_NODES) s += g_deg[idx];
    }
#pragma unroll
    for (int o = 16; o > 0; o >>= 1)
        s += __shfl_xor_sync(0xFFFFFFFFu, s, o);
    if (lane == 0) warpTot[w] = s;
    __syncthreads();

    if (w == 0) {
        int v = warpTot[lane];
        int p = v;
#pragma unroll
        for (int o = 1; o < 32; o <<= 1) {
            int t = __shfl_up_sync(0xFFFFFFFFu, p, o);
            if (lane >= o) p += t;
        }
        warpTot[lane] = p - v;
    }
    __syncthreads();

    int carry = warpTot[w];
#pragma unroll
    for (int i = 0; i < ITERS; i++) {
        int idx = base + i * 32 + lane;
        int v = (idx < N_NODES) ? g_deg[idx] : 0;
        int incl = v;
#pragma unroll
        for (int o = 1; o < 32; o <<= 1) {
            int t = __shfl_up_sync(0xFFFFFFFFu, incl, o);
            if (lane >= o) incl += t;
        }
        if (idx < N_NODES) {
            int e = carry + incl - v;
            g_off[idx] = e;
            g_cur[idx] = e;
        }
        carry += __shfl_sync(0xFFFFFFFFu, incl, 31);
    }
    if (tid == 0) g_off[N_NODES] = E_EDGES;
}

// scatter src ids into CSR order for dst in [dlo, dhi)
__global__ void scatter_kernel(const int* __restrict__ src,
                               const int* __restrict__ dst,
                               int dlo, int dhi)
{
    const int stride = gridDim.x * blockDim.x;
    for (int i = blockIdx.x * blockDim.x + threadIdx.x; i < E_EDGES; i += stride) {
        const int d = dst[i];
        if (d >= dlo && d < dhi) {
            const int p = atomicAdd(&g_cur[d], 1);
            g_esrc[p] = src[i];
        }
    }
}

// ---------------------------------------------------------------------------
// Tensor-core QKV GEMM (linear Q/K/V outputs)
// ---------------------------------------------------------------------------
constexpr int GBM = 64;
constexpr int LDA = 136;
constexpr int LDB = 72;

__global__ __launch_bounds__(256)
void qkv_hmma_kernel(const float* __restrict__ bq,
                     const float* __restrict__ bk,
                     const float* __restrict__ bv)
{
    __shared__ __half sA[GBM * LDA];
    __shared__ __half sB[DIN * LDB];

    const int tid  = threadIdx.x;
    const int lane = tid & 31;
    const int wid  = tid >> 5;
    const int row0 = blockIdx.x * GBM;
    const int by   = blockIdx.y;
    const int mat  = by >> 1;
    const int n0   = (by & 1) * 64;

    const float* bias = (mat == 0) ? bq : (mat == 1 ? bk : bv);
    __half*      outp = (mat == 0) ? g_Qh : (mat == 1 ? g_Kh : g_Vh);
    const __half* Wp  = g_Wh + mat * DIN * DIN;

#pragma unroll
    for (int p = 0; p < 4; p++) {
        int c   = tid + p * 256;
        int r   = c >> 4;
        int cc  = (c & 15) << 3;
        int gr  = row0 + r;
        if (gr >= N_NODES) gr = N_NODES - 1;
        uint4 v = *reinterpret_cast<const uint4*>(&g_hh[gr * DIN + cc]);
        *reinterpret_cast<uint4*>(&sA[r * LDA + cc]) = v;
    }
#pragma unroll
    for (int p = 0; p < 4; p++) {
        int c  = tid + p * 256;
        int r  = c >> 3;
        int cc = (c & 7) << 3;
        uint4 v = *reinterpret_cast<const uint4*>(&Wp[r * DIN + n0 + cc]);
        *reinterpret_cast<uint4*>(&sB[r * LDB + cc]) = v;
    }
    __syncthreads();

    const int wm = (wid & 3) * 16;
    const int wn = (wid >> 2) * 32;

    float acc[4][4];
#pragma unroll
    for (int t = 0; t < 4; t++)
#pragma unroll
        for (int r = 0; r < 4; r++) acc[t][r] = 0.f;

    const unsigned aBase = (unsigned)__cvta_generic_to_shared(sA);
    const unsigned bBase = (unsigned)__cvta_generic_to_shared(sB);

#pragma unroll
    for (int ks = 0; ks < 8; ks++) {
        const int k0 = ks * 16;
        unsigned a0, a1, a2, a3;
        {
            unsigned addr = aBase +
                ((wm + (lane & 15)) * LDA + k0 + ((lane >> 4) << 3)) * 2;
            asm volatile(
                "ldmatrix.sync.aligned.m8n8.x4.shared.b16 {%0,%1,%2,%3}, [%4];"
                : "=r"(a0), "=r"(a1), "=r"(a2), "=r"(a3) : "r"(addr));
        }
#pragma unroll
        for (int hf = 0; hf < 2; hf++) {
            const int nw = wn + hf * 16;
            unsigned b0, b1, b2, b3;
            unsigned addr = bBase +
                ((k0 + (lane & 15)) * LDB + nw + ((lane >> 4) << 3)) * 2;
            asm volatile(
                "ldmatrix.sync.aligned.m8n8.x4.trans.shared.b16 {%0,%1,%2,%3}, [%4];"
                : "=r"(b0), "=r"(b1), "=r"(b2), "=r"(b3) : "r"(addr));
            const int t0 = hf * 2;
            asm volatile(
                "mma.sync.aligned.m16n8k16.row.col.f32.f16.f16.f32 "
                "{%0,%1,%2,%3}, {%4,%5,%6,%7}, {%8,%9}, {%0,%1,%2,%3};"
                : "+f"(acc[t0][0]), "+f"(acc[t0][1]), "+f"(acc[t0][2]), "+f"(acc[t0][3])
                : "r"(a0), "r"(a1), "r"(a2), "r"(a3), "r"(b0), "r"(b1));
            asm volatile(
                "mma.sync.aligned.m16n8k16.row.col.f32.f16.f16.f32 "
                "{%0,%1,%2,%3}, {%4,%5,%6,%7}, {%8,%9}, {%0,%1,%2,%3};"
                : "+f"(acc[t0+1][0]), "+f"(acc[t0+1][1]), "+f"(acc[t0+1][2]), "+f"(acc[t0+1][3])
                : "r"(a0), "r"(a1), "r"(a2), "r"(a3), "r"(b2), "r"(b3));
        }
    }

    const int rr = lane >> 2;
    const int cc2 = (lane & 3) * 2;
#pragma unroll
    for (int t = 0; t < 4; t++) {
        const int gc = n0 + wn + t * 8 + cc2;
        const float b0f = bias[gc], b1f = bias[gc + 1];
        int gr0 = row0 + wm + rr;
        int gr1 = gr0 + 8;
        if (gr0 < N_NODES) {
            __half2 h2 = __floats2half2_rn(acc[t][0] + b0f, acc[t][1] + b1f);
            *reinterpret_cast<unsigned*>(&outp[gr0 * DIN + gc]) =
                *reinterpret_cast<unsigned*>(&h2);
        }
        if (gr1 < N_NODES) {
            __half2 h2 = __floats2half2_rn(acc[t][2] + b0f, acc[t][3] + b1f);
            *reinterpret_cast<unsigned*>(&outp[gr1 * DIN + gc]) =
                *reinterpret_cast<unsigned*>(&h2);
        }
    }
}

// ---------------------------------------------------------------------------
// CSR gather (R8/R13 version, with node-base offset). One warp per node.
// ---------------------------------------------------------------------------
__device__ __forceinline__ void edge_math(
    const uint2& kraw, const uint2& vraw, int lane,
    const float2& q0, const float2& q1,
    float& a0, float& a1, float& a2, float& a3, float& zsum)
{
    const float2 k0 = __half22float2(*reinterpret_cast<const __half2*>(&kraw.x));
    const float2 k1 = __half22float2(*reinterpret_cast<const __half2*>(&kraw.y));

    float part = k0.x * q0.x + k0.y * q0.y + k1.x * q1.x + k1.y * q1.y;
    part += __shfl_xor_sync(0xFFFFFFFFu, part, 1);
    part += __shfl_xor_sync(0xFFFFFFFFu, part, 2);

    float x = part * INV_SCALE;
    x = fminf(fmaxf(x, -5.0f), 5.0f);
    const float sc = __expf(x);

    const float2 v0 = __half22float2(*reinterpret_cast<const __half2*>(&vraw.x));
    const float2 v1 = __half22float2(*reinterpret_cast<const __half2*>(&vraw.y));

    a0 += v0.x * sc; a1 += v0.y * sc; a2 += v1.x * sc; a3 += v1.y * sc;
    zsum += sc;
}

__global__ __launch_bounds__(256)
void gather_kernel(float* __restrict__ out, int nodeBase, int nodeCount)
{
    const int nrel = (blockIdx.x * blockDim.x + threadIdx.x) >> 5;
    const int lane = threadIdx.x & 31;
    if (nrel >= nodeCount) return;
    const int node = nodeBase + nrel;

    const uint2 qraw = *reinterpret_cast<const uint2*>(&g_Qh[node * DIN + lane * 4]);
    const float2 q0 = __half22float2(*reinterpret_cast<const __half2*>(&qraw.x));
    const float2 q1 = __half22float2(*reinterpret_cast<const __half2*>(&qraw.y));

    const int j0 = g_off[node];
    const int j1 = g_off[node + 1];

    float a0 = 0.f, a1 = 0.f, a2 = 0.f, a3 = 0.f, zsum = 0.f;

    int j = j0;
    for (; j + 4 <= j1; j += 4) {
        const int s0 = g_esrc[j + 0];
        const int s1 = g_esrc[j + 1];
        const int s2 = g_esrc[j + 2];
        const int s3 = g_esrc[j + 3];
        const uint2 k0r = *reinterpret_cast<const uint2*>(&g_Kh[s0 * DIN + lane * 4]);
        const uint2 k1r = *reinterpret_cast<const uint2*>(&g_Kh[s1 * DIN + lane * 4]);
        const uint2 k2r = *reinterpret_cast<const uint2*>(&g_Kh[s2 * DIN + lane * 4]);
        const uint2 k3r = *reinterpret_cast<const uint2*>(&g_Kh[s3 * DIN + lane * 4]);
        const uint2 v0r = *reinterpret_cast<const uint2*>(&g_Vh[s0 * DIN + lane * 4]);
        const uint2 v1r = *reinterpret_cast<const uint2*>(&g_Vh[s1 * DIN + lane * 4]);
        const uint2 v2r = *reinterpret_cast<const uint2*>(&g_Vh[s2 * DIN + lane * 4]);
        const uint2 v3r = *reinterpret_cast<const uint2*>(&g_Vh[s3 * DIN + lane * 4]);
        edge_math(k0r, v0r, lane, q0, q1, a0, a1, a2, a3, zsum);
        edge_math(k1r, v1r, lane, q0, q1, a0, a1, a2, a3, zsum);
        edge_math(k2r, v2r, lane, q0, q1, a0, a1, a2, a3, zsum);
        edge_math(k3r, v3r, lane, q0, q1, a0, a1, a2, a3, zsum);
    }
    for (; j < j1; j++) {
        const int s = g_esrc[j];
        const uint2 kr = *reinterpret_cast<const uint2*>(&g_Kh[s * DIN + lane * 4]);
        const uint2 vr = *reinterpret_cast<const uint2*>(&g_Vh[s * DIN + lane * 4]);
        edge_math(kr, vr, lane, q0, q1, a0, a1, a2, a3, zsum);
    }

    const float zr = 1.0f / (zsum + 1e-6f);
    float4 o;
    o.x = a0 * zr; o.y = a1 * zr; o.z = a2 * zr; o.w = a3 * zr;
    *reinterpret_cast<float4*>(&out[node * DIN + lane * 4]) = o;
}

// ---------------------------------------------------------------------------
// Launch: fork CSR chain; scatter/gather split by dst halves for pipelining.
// ---------------------------------------------------------------------------
struct SideRes {
    cudaStream_t stream;
    cudaEvent_t  fork, joinLo, joinHi;
};
static SideRes make_side_res()
{
    SideRes r;
    cudaStreamCreateWithFlags(&r.stream, cudaStreamNonBlocking);
    cudaEventCreateWithFlags(&r.fork, cudaEventDisableTiming);
    cudaEventCreateWithFlags(&r.joinLo, cudaEventDisableTiming);
    cudaEventCreateWithFlags(&r.joinHi, cudaEventDisableTiming);
    return r;
}

extern "C" void kernel_launch(void* const* d_in, const int* in_sizes, int n_in,
                              void* d_out, int out_size)
{
    static SideRes sr = make_side_res();

    const float* h  = (const float*)d_in[0];
    const float* Wq = (const float*)d_in[1];
    const float* bq = (const float*)d_in[2];
    const float* Wk = (const float*)d_in[3];
    const float* bk = (const float*)d_in[4];
    const float* Wv = (const float*)d_in[5];
    const float* bv = (const float*)d_in[6];
    const int*   src = (const int*)d_in[7];
    const int*   dst = (const int*)d_in[8];
    float* out = (float*)d_out;

    // Fork: CSR chain on side stream, concurrent with convert+GEMM chain.
    cudaEventRecord(sr.fork, 0);
    cudaStreamWaitEvent(sr.stream, sr.fork, 0);

    zero_deg_kernel<<<(N_NODES + 255) / 256, 256, 0, sr.stream>>>();
    hist_kernel<<<1184, 256, 0, sr.stream>>>(dst);
    scan_kernel<<<1, 1024, 0, sr.stream>>>();
    scatter_kernel<<<1184, 256, 0, sr.stream>>>(src, dst, 0, N_HALF);
    cudaEventRecord(sr.joinLo, sr.stream);
    scatter_kernel<<<1184, 256, 0, sr.stream>>>(src, dst, N_HALF, N_NODES);
    cudaEventRecord(sr.joinHi, sr.stream);

    // Main stream: fp16 converts + tensor-core QKV projection.
    convert_h_kernel<<<(N_NODES * DIN / 4 + 255) / 256, 256>>>(h);
    convert_w_kernel<<<(3 * DIN * DIN / 4 + 255) / 256, 256>>>(Wq, Wk, Wv);
    dim3 ggrid((N_NODES + GBM - 1) / GBM, 6);
    qkv_hmma_kernel<<<ggrid, 256>>>(bq, bk, bv);

    // gather_lo overlaps scatter_hi; gather_hi follows.
    cudaStreamWaitEvent(0, sr.joinLo, 0);
    gather_kernel<<<N_HALF / 8, 256>>>(out, 0, N_HALF);
    cudaStreamWaitEvent(0, sr.joinHi, 0);
    gather_kernel<<<(N_NODES - N_HALF + 7) / 8, 256>>>(out, N_HALF, N_NODES - N_HALF);
}

// round 16
// speedup vs baseline: 1.0256x; 1.0256x over previous
#include <cuda_runtime.h>
#include <cuda_fp16.h>
#include <math.h>

// Problem constants (fixed by the dataset)
constexpr int N_NODES = 50000;
constexpr int E_EDGES = 800000;
constexpr int DIN     = 128;      // also H*D_HEAD
constexpr int NHEAD   = 8;
constexpr float INV_SCALE = 0.25f;   // 1/sqrt(16)

// Scratch (device globals — no allocation allowed).
__device__ __half g_hh[N_NODES * DIN];        // h in fp16
__device__ __half g_Wh[3 * DIN * DIN];        // Wq|Wk|Wv in fp16
__device__ __half g_Qh[N_NODES * DIN];
__device__ __half g_Kh[N_NODES * DIN];
__device__ __half g_Vh[N_NODES * DIN];
// CSR-by-dst structures
__device__ int g_deg[N_NODES];
__device__ int g_cur[N_NODES];
__device__ int g_off[N_NODES + 1];
__device__ int g_esrc[E_EDGES];

// ---------------------------------------------------------------------------
// Converters: fp32 -> fp16
// ---------------------------------------------------------------------------
__global__ void convert_h_kernel(const float* __restrict__ h)
{
    const int i = (blockIdx.x * blockDim.x + threadIdx.x) * 4;
    if (i >= N_NODES * DIN) return;
    float4 v = *reinterpret_cast<const float4*>(&h[i]);
    __half2 lo = __floats2half2_rn(v.x, v.y);
    __half2 hi = __floats2half2_rn(v.z, v.w);
    uint2 p;
    p.x = *reinterpret_cast<unsigned*>(&lo);
    p.y = *reinterpret_cast<unsigned*>(&hi);
    *reinterpret_cast<uint2*>(&g_hh[i]) = p;
}

__global__ void convert_w_kernel(const float* __restrict__ Wq,
                                 const float* __restrict__ Wk,
                                 const float* __restrict__ Wv)
{
    const int i = (blockIdx.x * blockDim.x + threadIdx.x) * 4;
    if (i >= 3 * DIN * DIN) return;
    const int mat = i >> 14;
    const int off = i & 16383;
    const float* W = (mat == 0) ? Wq : (mat == 1 ? Wk : Wv);
    float4 v = *reinterpret_cast<const float4*>(&W[off]);
    __half2 lo = __floats2half2_rn(v.x, v.y);
    __half2 hi = __floats2half2_rn(v.z, v.w);
    uint2 p;
    p.x = *reinterpret_cast<unsigned*>(&lo);
    p.y = *reinterpret_cast<unsigned*>(&hi);
    *reinterpret_cast<uint2*>(&g_Wh[i]) = p;
}

// ---------------------------------------------------------------------------
// CSR build
// ---------------------------------------------------------------------------
__global__ void zero_deg_kernel()
{
    int i = blockIdx.x * blockDim.x + threadIdx.x;
    if (i < N_NODES) g_deg[i] = 0;
}

// single-pass histogram: one int4 (4 edges) per thread, 4 independent REDG
__global__ void hist_kernel(const int* __restrict__ dst)
{
    const int i = blockIdx.x * blockDim.x + threadIdx.x;
    if (i >= E_EDGES / 4) return;
    int4 d = reinterpret_cast<const int4*>(dst)[i];
    atomicAdd(&g_deg[d.x], 1);
    atomicAdd(&g_deg[d.y], 1);
    atomicAdd(&g_deg[d.z], 1);
    atomicAdd(&g_deg[d.w], 1);
}

// Coalesced single-block scan; seeds g_cur = g_off.
__global__ __launch_bounds__(1024)
void scan_kernel()
{
    constexpr int WREG  = 1568;            // 49 * 32
    constexpr int ITERS = WREG / 32;       // 49
    __shared__ int warpTot[32];

    const int tid  = threadIdx.x;
    const int lane = tid & 31;
    const int w    = tid >> 5;
    const int base = w * WREG;

    int s = 0;
#pragma unroll
    for (int i = 0; i < ITERS; i++) {
        int idx = base + i * 32 + lane;
        if (idx < N_NODES) s += g_deg[idx];
    }
#pragma unroll
    for (int o = 16; o > 0; o >>= 1)
        s += __shfl_xor_sync(0xFFFFFFFFu, s, o);
    if (lane == 0) warpTot[w] = s;
    __syncthreads();

    if (w == 0) {
        int v = warpTot[lane];
        int p = v;
#pragma unroll
        for (int o = 1; o < 32; o <<= 1) {
            int t = __shfl_up_sync(0xFFFFFFFFu, p, o);
            if (lane >= o) p += t;
        }
        warpTot[lane] = p - v;
    }
    __syncthreads();

    int carry = warpTot[w];
#pragma unroll
    for (int i = 0; i < ITERS; i++) {
        int idx = base + i * 32 + lane;
        int v = (idx < N_NODES) ? g_deg[idx] : 0;
        int incl = v;
#pragma unroll
        for (int o = 1; o < 32; o <<= 1) {
            int t = __shfl_up_sync(0xFFFFFFFFu, incl, o);
            if (lane >= o) incl += t;
        }
        if (idx < N_NODES) {
            int e = carry + incl - v;
            g_off[idx] = e;
            g_cur[idx] = e;
        }
        carry += __shfl_sync(0xFFFFFFFFu, incl, 31);
    }
    if (tid == 0) g_off[N_NODES] = E_EDGES;
}

// single-pass scatter: one edge per thread (max TLP hides atomic latency)
__global__ void scatter_kernel(const int* __restrict__ src,
                               const int* __restrict__ dst)
{
    const int i = blockIdx.x * blockDim.x + threadIdx.x;
    if (i >= E_EDGES) return;
    const int p = atomicAdd(&g_cur[dst[i]], 1);
    g_esrc[p] = src[i];
}

// ---------------------------------------------------------------------------
// Tensor-core QKV GEMM (linear Q/K/V outputs)
// ---------------------------------------------------------------------------
constexpr int GBM = 64;
constexpr int LDA = 136;
constexpr int LDB = 72;

__global__ __launch_bounds__(256)
void qkv_hmma_kernel(const float* __restrict__ bq,
                     const float* __restrict__ bk,
                     const float* __restrict__ bv)
{
    __shared__ __half sA[GBM * LDA];
    __shared__ __half sB[DIN * LDB];

    const int tid  = threadIdx.x;
    const int lane = tid & 31;
    const int wid  = tid >> 5;
    const int row0 = blockIdx.x * GBM;
    const int by   = blockIdx.y;
    const int mat  = by >> 1;
    const int n0   = (by & 1) * 64;

    const float* bias = (mat == 0) ? bq : (mat == 1 ? bk : bv);
    __half*      outp = (mat == 0) ? g_Qh : (mat == 1 ? g_Kh : g_Vh);
    const __half* Wp  = g_Wh + mat * DIN * DIN;

#pragma unroll
    for (int p = 0; p < 4; p++) {
        int c   = tid + p * 256;
        int r   = c >> 4;
        int cc  = (c & 15) << 3;
        int gr  = row0 + r;
        if (gr >= N_NODES) gr = N_NODES - 1;
        uint4 v = *reinterpret_cast<const uint4*>(&g_hh[gr * DIN + cc]);
        *reinterpret_cast<uint4*>(&sA[r * LDA + cc]) = v;
    }
#pragma unroll
    for (int p = 0; p < 4; p++) {
        int c  = tid + p * 256;
        int r  = c >> 3;
        int cc = (c & 7) << 3;
        uint4 v = *reinterpret_cast<const uint4*>(&Wp[r * DIN + n0 + cc]);
        *reinterpret_cast<uint4*>(&sB[r * LDB + cc]) = v;
    }
    __syncthreads();

    const int wm = (wid & 3) * 16;
    const int wn = (wid >> 2) * 32;

    float acc[4][4];
#pragma unroll
    for (int t = 0; t < 4; t++)
#pragma unroll
        for (int r = 0; r < 4; r++) acc[t][r] = 0.f;

    const unsigned aBase = (unsigned)__cvta_generic_to_shared(sA);
    const unsigned bBase = (unsigned)__cvta_generic_to_shared(sB);

#pragma unroll
    for (int ks = 0; ks < 8; ks++) {
        const int k0 = ks * 16;
        unsigned a0, a1, a2, a3;
        {
            unsigned addr = aBase +
                ((wm + (lane & 15)) * LDA + k0 + ((lane >> 4) << 3)) * 2;
            asm volatile(
                "ldmatrix.sync.aligned.m8n8.x4.shared.b16 {%0,%1,%2,%3}, [%4];"
                : "=r"(a0), "=r"(a1), "=r"(a2), "=r"(a3) : "r"(addr));
        }
#pragma unroll
        for (int hf = 0; hf < 2; hf++) {
            const int nw = wn + hf * 16;
            unsigned b0, b1, b2, b3;
            unsigned addr = bBase +
                ((k0 + (lane & 15)) * LDB + nw + ((lane >> 4) << 3)) * 2;
            asm volatile(
                "ldmatrix.sync.aligned.m8n8.x4.trans.shared.b16 {%0,%1,%2,%3}, [%4];"
                : "=r"(b0), "=r"(b1), "=r"(b2), "=r"(b3) : "r"(addr));
            const int t0 = hf * 2;
            asm volatile(
                "mma.sync.aligned.m16n8k16.row.col.f32.f16.f16.f32 "
                "{%0,%1,%2,%3}, {%4,%5,%6,%7}, {%8,%9}, {%0,%1,%2,%3};"
                : "+f"(acc[t0][0]), "+f"(acc[t0][1]), "+f"(acc[t0][2]), "+f"(acc[t0][3])
                : "r"(a0), "r"(a1), "r"(a2), "r"(a3), "r"(b0), "r"(b1));
            asm volatile(
                "mma.sync.aligned.m16n8k16.row.col.f32.f16.f16.f32 "
                "{%0,%1,%2,%3}, {%4,%5,%6,%7}, {%8,%9}, {%0,%1,%2,%3};"
                : "+f"(acc[t0+1][0]), "+f"(acc[t0+1][1]), "+f"(acc[t0+1][2]), "+f"(acc[t0+1][3])
                : "r"(a0), "r"(a1), "r"(a2), "r"(a3), "r"(b2), "r"(b3));
        }
    }

    const int rr = lane >> 2;
    const int cc2 = (lane & 3) * 2;
#pragma unroll
    for (int t = 0; t < 4; t++) {
        const int gc = n0 + wn + t * 8 + cc2;
        const float b0f = bias[gc], b1f = bias[gc + 1];
        int gr0 = row0 + wm + rr;
        int gr1 = gr0 + 8;
        if (gr0 < N_NODES) {
            __half2 h2 = __floats2half2_rn(acc[t][0] + b0f, acc[t][1] + b1f);
            *reinterpret_cast<unsigned*>(&outp[gr0 * DIN + gc]) =
                *reinterpret_cast<unsigned*>(&h2);
        }
        if (gr1 < N_NODES) {
            __half2 h2 = __floats2half2_rn(acc[t][2] + b0f, acc[t][3] + b1f);
            *reinterpret_cast<unsigned*>(&outp[gr1 * DIN + gc]) =
                *reinterpret_cast<unsigned*>(&h2);
        }
    }
}

// ---------------------------------------------------------------------------
// CSR gather (R13 version). One warp per node. Batch-4 edges for MLP.
// ---------------------------------------------------------------------------
__device__ __forceinline__ void edge_math(
    const uint2& kraw, const uint2& vraw, int lane,
    const float2& q0, const float2& q1,
    float& a0, float& a1, float& a2, float& a3, float& zsum)
{
    const float2 k0 = __half22float2(*reinterpret_cast<const __half2*>(&kraw.x));
    const float2 k1 = __half22float2(*reinterpret_cast<const __half2*>(&kraw.y));

    float part = k0.x * q0.x + k0.y * q0.y + k1.x * q1.x + k1.y * q1.y;
    part += __shfl_xor_sync(0xFFFFFFFFu, part, 1);
    part += __shfl_xor_sync(0xFFFFFFFFu, part, 2);

    float x = part * INV_SCALE;
    x = fminf(fmaxf(x, -5.0f), 5.0f);
    const float sc = __expf(x);

    const float2 v0 = __half22float2(*reinterpret_cast<const __half2*>(&vraw.x));
    const float2 v1 = __half22float2(*reinterpret_cast<const __half2*>(&vraw.y));

    a0 += v0.x * sc; a1 += v0.y * sc; a2 += v1.x * sc; a3 += v1.y * sc;
    zsum += sc;
}

__global__ __launch_bounds__(256)
void gather_kernel(float* __restrict__ out)
{
    const int node = (blockIdx.x * blockDim.x + threadIdx.x) >> 5;
    const int lane = threadIdx.x & 31;
    if (node >= N_NODES) return;

    const uint2 qraw = *reinterpret_cast<const uint2*>(&g_Qh[node * DIN + lane * 4]);
    const float2 q0 = __half22float2(*reinterpret_cast<const __half2*>(&qraw.x));
    const float2 q1 = __half22float2(*reinterpret_cast<const __half2*>(&qraw.y));

    const int j0 = g_off[node];
    const int j1 = g_off[node + 1];

    float a0 = 0.f, a1 = 0.f, a2 = 0.f, a3 = 0.f, zsum = 0.f;

    int j = j0;
    for (; j + 4 <= j1; j += 4) {
        const int s0 = g_esrc[j + 0];
        const int s1 = g_esrc[j + 1];
        const int s2 = g_esrc[j + 2];
        const int s3 = g_esrc[j + 3];
        const uint2 k0r = *reinterpret_cast<const uint2*>(&g_Kh[s0 * DIN + lane * 4]);
        const uint2 k1r = *reinterpret_cast<const uint2*>(&g_Kh[s1 * DIN + lane * 4]);
        const uint2 k2r = *reinterpret_cast<const uint2*>(&g_Kh[s2 * DIN + lane * 4]);
        const uint2 k3r = *reinterpret_cast<const uint2*>(&g_Kh[s3 * DIN + lane * 4]);
        const uint2 v0r = *reinterpret_cast<const uint2*>(&g_Vh[s0 * DIN + lane * 4]);
        const uint2 v1r = *reinterpret_cast<const uint2*>(&g_Vh[s1 * DIN + lane * 4]);
        const uint2 v2r = *reinterpret_cast<const uint2*>(&g_Vh[s2 * DIN + lane * 4]);
        const uint2 v3r = *reinterpret_cast<const uint2*>(&g_Vh[s3 * DIN + lane * 4]);
        edge_math(k0r, v0r, lane, q0, q1, a0, a1, a2, a3, zsum);
        edge_math(k1r, v1r, lane, q0, q1, a0, a1, a2, a3, zsum);
        edge_math(k2r, v2r, lane, q0, q1, a0, a1, a2, a3, zsum);
        edge_math(k3r, v3r, lane, q0, q1, a0, a1, a2, a3, zsum);
    }
    for (; j < j1; j++) {
        const int s = g_esrc[j];
        const uint2 kr = *reinterpret_cast<const uint2*>(&g_Kh[s * DIN + lane * 4]);
        const uint2 vr = *reinterpret_cast<const uint2*>(&g_Vh[s * DIN + lane * 4]);
        edge_math(kr, vr, lane, q0, q1, a0, a1, a2, a3, zsum);
    }

    const float zr = 1.0f / (zsum + 1e-6f);
    float4 o;
    o.x = a0 * zr; o.y = a1 * zr; o.z = a2 * zr; o.w = a3 * zr;
    *reinterpret_cast<float4*>(&out[node * DIN + lane * 4]) = o;
}

// ---------------------------------------------------------------------------
// Launch: fork CSR chain onto a side stream, join before gather.
// ---------------------------------------------------------------------------
struct SideRes {
    cudaStream_t stream;
    cudaEvent_t  fork, join;
};
static SideRes make_side_res()
{
    SideRes r;
    cudaStreamCreateWithFlags(&r.stream, cudaStreamNonBlocking);
    cudaEventCreateWithFlags(&r.fork, cudaEventDisableTiming);
    cudaEventCreateWithFlags(&r.join, cudaEventDisableTiming);
    return r;
}

extern "C" void kernel_launch(void* const* d_in, const int* in_sizes, int n_in,
                              void* d_out, int out_size)
{
    static SideRes sr = make_side_res();

    const float* h  = (const float*)d_in[0];
    const float* Wq = (const float*)d_in[1];
    const float* bq = (const float*)d_in[2];
    const float* Wk = (const float*)d_in[3];
    const float* bk = (const float*)d_in[4];
    const float* Wv = (const float*)d_in[5];
    const float* bv = (const float*)d_in[6];
    const int*   src = (const int*)d_in[7];
    const int*   dst = (const int*)d_in[8];
    float* out = (float*)d_out;

    // Fork: CSR chain on side stream, concurrent with convert+GEMM chain.
    cudaEventRecord(sr.fork, 0);
    cudaStreamWaitEvent(sr.stream, sr.fork, 0);

    zero_deg_kernel<<<(N_NODES + 255) / 256, 256, 0, sr.stream>>>();
    hist_kernel<<<(E_EDGES / 4 + 255) / 256, 256, 0, sr.stream>>>(dst);      // 782 blocks, single pass
    scan_kernel<<<1, 1024, 0, sr.stream>>>();
    scatter_kernel<<<(E_EDGES + 255) / 256, 256, 0, sr.stream>>>(src, dst);  // 3125 blocks, 1 edge/thread
    cudaEventRecord(sr.join, sr.stream);

    // Main stream: fp16 converts + tensor-core QKV projection.
    convert_h_kernel<<<(N_NODES * DIN / 4 + 255) / 256, 256>>>(h);
    convert_w_kernel<<<(3 * DIN * DIN / 4 + 255) / 256, 256>>>(Wq, Wk, Wv);
    dim3 ggrid((N_NODES + GBM - 1) / GBM, 6);
    qkv_hmma_kernel<<<ggrid, 256>>>(bq, bk, bv);

    // Join, then gather: one warp per node, 8 nodes per block.
    cudaStreamWaitEvent(0, sr.join, 0);
    gather_kernel<<<(N_NODES + 7) / 8, 256>>>(out);
}

// round 17
// speedup vs baseline: 1.0522x; 1.0260x over previous
#include <cuda_runtime.h>
#include <cuda_fp16.h>
#include <math.h>

// Problem constants (fixed by the dataset)
constexpr int N_NODES = 50000;
constexpr int E_EDGES = 800000;
constexpr int DIN     = 128;      // also H*D_HEAD
constexpr int NHEAD   = 8;
constexpr float INV_SCALE = 0.25f;   // 1/sqrt(16)

// Scratch (device globals — no allocation allowed).
__device__ __half g_Wh[3 * DIN * DIN];        // Wq|Wk|Wv in fp16
__device__ __half g_Qh[N_NODES * DIN];
__device__ __half g_Kh[N_NODES * DIN];
__device__ __half g_Vh[N_NODES * DIN];
// CSR-by-dst structures
__device__ int g_deg[N_NODES];
__device__ int g_cur[N_NODES];
__device__ int g_off[N_NODES + 1];
__device__ int g_esrc[E_EDGES];

// ---------------------------------------------------------------------------
// Converter: W fp32 -> fp16 (h conversion is fused into the GEMM)
// ---------------------------------------------------------------------------
__global__ void convert_w_kernel(const float* __restrict__ Wq,
                                 const float* __restrict__ Wk,
                                 const float* __restrict__ Wv)
{
    const int i = (blockIdx.x * blockDim.x + threadIdx.x) * 4;
    if (i >= 3 * DIN * DIN) return;
    const int mat = i >> 14;
    const int off = i & 16383;
    const float* W = (mat == 0) ? Wq : (mat == 1 ? Wk : Wv);
    float4 v = *reinterpret_cast<const float4*>(&W[off]);
    __half2 lo = __floats2half2_rn(v.x, v.y);
    __half2 hi = __floats2half2_rn(v.z, v.w);
    uint2 p;
    p.x = *reinterpret_cast<unsigned*>(&lo);
    p.y = *reinterpret_cast<unsigned*>(&hi);
    *reinterpret_cast<uint2*>(&g_Wh[i]) = p;
}

// ---------------------------------------------------------------------------
// CSR build
// ---------------------------------------------------------------------------
__global__ void zero_deg_kernel()
{
    int i = blockIdx.x * blockDim.x + threadIdx.x;
    if (i < N_NODES) g_deg[i] = 0;
}

// single-pass histogram: one int4 (4 edges) per thread, 4 independent REDG
__global__ void hist_kernel(const int* __restrict__ dst)
{
    const int i = blockIdx.x * blockDim.x + threadIdx.x;
    if (i >= E_EDGES / 4) return;
    int4 d = reinterpret_cast<const int4*>(dst)[i];
    atomicAdd(&g_deg[d.x], 1);
    atomicAdd(&g_deg[d.y], 1);
    atomicAdd(&g_deg[d.z], 1);
    atomicAdd(&g_deg[d.w], 1);
}

// Coalesced single-block scan; seeds g_cur = g_off.
__global__ __launch_bounds__(1024)
void scan_kernel()
{
    constexpr int WREG  = 1568;            // 49 * 32
    constexpr int ITERS = WREG / 32;       // 49
    __shared__ int warpTot[32];

    const int tid  = threadIdx.x;
    const int lane = tid & 31;
    const int w    = tid >> 5;
    const int base = w * WREG;

    int s = 0;
#pragma unroll
    for (int i = 0; i < ITERS; i++) {
        int idx = base + i * 32 + lane;
        if (idx < N_NODES) s += g_deg[idx];
    }
#pragma unroll
    for (int o = 16; o > 0; o >>= 1)
        s += __shfl_xor_sync(0xFFFFFFFFu, s, o);
    if (lane == 0) warpTot[w] = s;
    __syncthreads();

    if (w == 0) {
        int v = warpTot[lane];
        int p = v;
#pragma unroll
        for (int o = 1; o < 32; o <<= 1) {
            int t = __shfl_up_sync(0xFFFFFFFFu, p, o);
            if (lane >= o) p += t;
        }
        warpTot[lane] = p - v;
    }
    __syncthreads();

    int carry = warpTot[w];
#pragma unroll
    for (int i = 0; i < ITERS; i++) {
        int idx = base + i * 32 + lane;
        int v = (idx < N_NODES) ? g_deg[idx] : 0;
        int incl = v;
#pragma unroll
        for (int o = 1; o < 32; o <<= 1) {
            int t = __shfl_up_sync(0xFFFFFFFFu, incl, o);
            if (lane >= o) incl += t;
        }
        if (idx < N_NODES) {
            int e = carry + incl - v;
            g_off[idx] = e;
            g_cur[idx] = e;
        }
        carry += __shfl_sync(0xFFFFFFFFu, incl, 31);
    }
    if (tid == 0) g_off[N_NODES] = E_EDGES;
}

// single-pass scatter: one edge per thread
__global__ void scatter_kernel(const int* __restrict__ src,
                               const int* __restrict__ dst)
{
    const int i = blockIdx.x * blockDim.x + threadIdx.x;
    if (i >= E_EDGES) return;
    const int p = atomicAdd(&g_cur[dst[i]], 1);
    g_esrc[p] = src[i];
}

// ---------------------------------------------------------------------------
// Fused tensor-core QKV GEMM: one block per 64-row tile; A loaded ONCE from
// fp32 h (converted to fp16 in-register); loops over 6 (mat, half) outputs.
// ---------------------------------------------------------------------------
constexpr int GBM = 64;
constexpr int LDA = 136;
constexpr int LDB = 72;

__global__ __launch_bounds__(256)
void qkv_hmma_kernel(const float* __restrict__ h,
                     const float* __restrict__ bq,
                     const float* __restrict__ bk,
                     const float* __restrict__ bv)
{
    __shared__ __half sA[GBM * LDA];
    __shared__ __half sB[DIN * LDB];

    const int tid  = threadIdx.x;
    const int lane = tid & 31;
    const int wid  = tid >> 5;
    const int row0 = blockIdx.x * GBM;

    // --- load A tile once: 64 rows x 128 fp32 -> fp16 smem ---
#pragma unroll
    for (int p = 0; p < 8; p++) {
        int c  = tid + p * 256;            // 0..2047 float4 slots
        int r  = c >> 5;                   // 0..63
        int cc = (c & 31) * 4;             // 0..124
        int gr = row0 + r;
        if (gr >= N_NODES) gr = N_NODES - 1;
        float4 v = *reinterpret_cast<const float4*>(&h[gr * DIN + cc]);
        __half2 lo = __floats2half2_rn(v.x, v.y);
        __half2 hi = __floats2half2_rn(v.z, v.w);
        uint2 pk;
        pk.x = *reinterpret_cast<unsigned*>(&lo);
        pk.y = *reinterpret_cast<unsigned*>(&hi);
        *reinterpret_cast<uint2*>(&sA[r * LDA + cc]) = pk;
    }

    const int wm = (wid & 3) * 16;
    const int wn = (wid >> 2) * 32;
    const int rr = lane >> 2;
    const int cc2 = (lane & 3) * 2;

    const unsigned aBase = (unsigned)__cvta_generic_to_shared(sA);
    const unsigned bBase = (unsigned)__cvta_generic_to_shared(sB);

    for (int phase = 0; phase < 6; phase++) {
        const int mat = phase >> 1;            // 0=Q, 1=K, 2=V
        const int n0  = (phase & 1) * 64;
        const float* bias = (mat == 0) ? bq : (mat == 1 ? bk : bv);
        __half*      outp = (mat == 0) ? g_Qh : (mat == 1 ? g_Kh : g_Vh);
        const __half* Wp  = g_Wh + mat * DIN * DIN;

        __syncthreads();   // protect sB reuse (and sA on first iteration)
        // load B tile: 128 k-rows x 64 halves
#pragma unroll
        for (int p = 0; p < 4; p++) {
            int c  = tid + p * 256;
            int r  = c >> 3;
            int cc = (c & 7) << 3;
            uint4 v = *reinterpret_cast<const uint4*>(&Wp[r * DIN + n0 + cc]);
            *reinterpret_cast<uint4*>(&sB[r * LDB + cc]) = v;
        }
        __syncthreads();

        float acc[4][4];
#pragma unroll
        for (int t = 0; t < 4; t++)
#pragma unroll
            for (int r = 0; r < 4; r++) acc[t][r] = 0.f;

#pragma unroll
        for (int ks = 0; ks < 8; ks++) {
            const int k0 = ks * 16;
            unsigned a0, a1, a2, a3;
            {
                unsigned addr = aBase +
                    ((wm + (lane & 15)) * LDA + k0 + ((lane >> 4) << 3)) * 2;
                asm volatile(
                    "ldmatrix.sync.aligned.m8n8.x4.shared.b16 {%0,%1,%2,%3}, [%4];"
                    : "=r"(a0), "=r"(a1), "=r"(a2), "=r"(a3) : "r"(addr));
            }
#pragma unroll
            for (int hf = 0; hf < 2; hf++) {
                const int nw = wn + hf * 16;
                unsigned b0, b1, b2, b3;
                unsigned addr = bBase +
                    ((k0 + (lane & 15)) * LDB + nw + ((lane >> 4) << 3)) * 2;
                asm volatile(
                    "ldmatrix.sync.aligned.m8n8.x4.trans.shared.b16 {%0,%1,%2,%3}, [%4];"
                    : "=r"(b0), "=r"(b1), "=r"(b2), "=r"(b3) : "r"(addr));
                const int t0 = hf * 2;
                asm volatile(
                    "mma.sync.aligned.m16n8k16.row.col.f32.f16.f16.f32 "
                    "{%0,%1,%2,%3}, {%4,%5,%6,%7}, {%8,%9}, {%0,%1,%2,%3};"
                    : "+f"(acc[t0][0]), "+f"(acc[t0][1]), "+f"(acc[t0][2]), "+f"(acc[t0][3])
                    : "r"(a0), "r"(a1), "r"(a2), "r"(a3), "r"(b0), "r"(b1));
                asm volatile(
                    "mma.sync.aligned.m16n8k16.row.col.f32.f16.f16.f32 "
                    "{%0,%1,%2,%3}, {%4,%5,%6,%7}, {%8,%9}, {%0,%1,%2,%3};"
                    : "+f"(acc[t0+1][0]), "+f"(acc[t0+1][1]), "+f"(acc[t0+1][2]), "+f"(acc[t0+1][3])
                    : "r"(a0), "r"(a1), "r"(a2), "r"(a3), "r"(b2), "r"(b3));
            }
        }

        // epilogue
#pragma unroll
        for (int t = 0; t < 4; t++) {
            const int gc = n0 + wn + t * 8 + cc2;
            const float b0f = bias[gc], b1f = bias[gc + 1];
            int gr0 = row0 + wm + rr;
            int gr1 = gr0 + 8;
            if (gr0 < N_NODES) {
                __half2 h2 = __floats2half2_rn(acc[t][0] + b0f, acc[t][1] + b1f);
                *reinterpret_cast<unsigned*>(&outp[gr0 * DIN + gc]) =
                    *reinterpret_cast<unsigned*>(&h2);
            }
            if (gr1 < N_NODES) {
                __half2 h2 = __floats2half2_rn(acc[t][2] + b0f, acc[t][3] + b1f);
                *reinterpret_cast<unsigned*>(&outp[gr1 * DIN + gc]) =
                    *reinterpret_cast<unsigned*>(&h2);
            }
        }
    }
}

// ---------------------------------------------------------------------------
// CSR gather (R13/R16 version). One warp per node. Batch-4 edges for MLP.
// ---------------------------------------------------------------------------
__device__ __forceinline__ void edge_math(
    const uint2& kraw, const uint2& vraw, int lane,
    const float2& q0, const float2& q1,
    float& a0, float& a1, float& a2, float& a3, float& zsum)
{
    const float2 k0 = __half22float2(*reinterpret_cast<const __half2*>(&kraw.x));
    const float2 k1 = __half22float2(*reinterpret_cast<const __half2*>(&kraw.y));

    float part = k0.x * q0.x + k0.y * q0.y + k1.x * q1.x + k1.y * q1.y;
    part += __shfl_xor_sync(0xFFFFFFFFu, part, 1);
    part += __shfl_xor_sync(0xFFFFFFFFu, part, 2);

    float x = part * INV_SCALE;
    x = fminf(fmaxf(x, -5.0f), 5.0f);
    const float sc = __expf(x);

    const float2 v0 = __half22float2(*reinterpret_cast<const __half2*>(&vraw.x));
    const float2 v1 = __half22float2(*reinterpret_cast<const __half2*>(&vraw.y));

    a0 += v0.x * sc; a1 += v0.y * sc; a2 += v1.x * sc; a3 += v1.y * sc;
    zsum += sc;
}

__global__ __launch_bounds__(256)
void gather_kernel(float* __restrict__ out)
{
    const int node = (blockIdx.x * blockDim.x + threadIdx.x) >> 5;
    const int lane = threadIdx.x & 31;
    if (node >= N_NODES) return;

    const uint2 qraw = *reinterpret_cast<const uint2*>(&g_Qh[node * DIN + lane * 4]);
    const float2 q0 = __half22float2(*reinterpret_cast<const __half2*>(&qraw.x));
    const float2 q1 = __half22float2(*reinterpret_cast<const __half2*>(&qraw.y));

    const int j0 = g_off[node];
    const int j1 = g_off[node + 1];

    float a0 = 0.f, a1 = 0.f, a2 = 0.f, a3 = 0.f, zsum = 0.f;

    int j = j0;
    for (; j + 4 <= j1; j += 4) {
        const int s0 = g_esrc[j + 0];
        const int s1 = g_esrc[j + 1];
        const int s2 = g_esrc[j + 2];
        const int s3 = g_esrc[j + 3];
        const uint2 k0r = *reinterpret_cast<const uint2*>(&g_Kh[s0 * DIN + lane * 4]);
        const uint2 k1r = *reinterpret_cast<const uint2*>(&g_Kh[s1 * DIN + lane * 4]);
        const uint2 k2r = *reinterpret_cast<const uint2*>(&g_Kh[s2 * DIN + lane * 4]);
        const uint2 k3r = *reinterpret_cast<const uint2*>(&g_Kh[s3 * DIN + lane * 4]);
        const uint2 v0r = *reinterpret_cast<const uint2*>(&g_Vh[s0 * DIN + lane * 4]);
        const uint2 v1r = *reinterpret_cast<const uint2*>(&g_Vh[s1 * DIN + lane * 4]);
        const uint2 v2r = *reinterpret_cast<const uint2*>(&g_Vh[s2 * DIN + lane * 4]);
        const uint2 v3r = *reinterpret_cast<const uint2*>(&g_Vh[s3 * DIN + lane * 4]);
        edge_math(k0r, v0r, lane, q0, q1, a0, a1, a2, a3, zsum);
        edge_math(k1r, v1r, lane, q0, q1, a0, a1, a2, a3, zsum);
        edge_math(k2r, v2r, lane, q0, q1, a0, a1, a2, a3, zsum);
        edge_math(k3r, v3r, lane, q0, q1, a0, a1, a2, a3, zsum);
    }
    for (; j < j1; j++) {
        const int s = g_esrc[j];
        const uint2 kr = *reinterpret_cast<const uint2*>(&g_Kh[s * DIN + lane * 4]);
        const uint2 vr = *reinterpret_cast<const uint2*>(&g_Vh[s * DIN + lane * 4]);
        edge_math(kr, vr, lane, q0, q1, a0, a1, a2, a3, zsum);
    }

    const float zr = 1.0f / (zsum + 1e-6f);
    float4 o;
    o.x = a0 * zr; o.y = a1 * zr; o.z = a2 * zr; o.w = a3 * zr;
    *reinterpret_cast<float4*>(&out[node * DIN + lane * 4]) = o;
}

// ---------------------------------------------------------------------------
// Launch: fork CSR chain onto a side stream, join before gather.
// ---------------------------------------------------------------------------
struct SideRes {
    cudaStream_t stream;
    cudaEvent_t  fork, join;
};
static SideRes make_side_res()
{
    SideRes r;
    cudaStreamCreateWithFlags(&r.stream, cudaStreamNonBlocking);
    cudaEventCreateWithFlags(&r.fork, cudaEventDisableTiming);
    cudaEventCreateWithFlags(&r.join, cudaEventDisableTiming);
    return r;
}

extern "C" void kernel_launch(void* const* d_in, const int* in_sizes, int n_in,
                              void* d_out, int out_size)
{
    static SideRes sr = make_side_res();

    const float* h  = (const float*)d_in[0];
    const float* Wq = (const float*)d_in[1];
    const float* bq = (const float*)d_in[2];
    const float* Wk = (const float*)d_in[3];
    const float* bk = (const float*)d_in[4];
    const float* Wv = (const float*)d_in[5];
    const float* bv = (const float*)d_in[6];
    const int*   src = (const int*)d_in[7];
    const int*   dst = (const int*)d_in[8];
    float* out = (float*)d_out;

    // Fork: CSR chain on side stream, concurrent with convert+GEMM chain.
    cudaEventRecord(sr.fork, 0);
    cudaStreamWaitEvent(sr.stream, sr.fork, 0);

    zero_deg_kernel<<<(N_NODES + 255) / 256, 256, 0, sr.stream>>>();
    hist_kernel<<<(E_EDGES / 4 + 255) / 256, 256, 0, sr.stream>>>(dst);
    scan_kernel<<<1, 1024, 0, sr.stream>>>();
    scatter_kernel<<<(E_EDGES + 255) / 256, 256, 0, sr.stream>>>(src, dst);
    cudaEventRecord(sr.join, sr.stream);

    // Main stream: W convert + fused (h-convert + QKV) tensor-core GEMM.
    convert_w_kernel<<<(3 * DIN * DIN / 4 + 255) / 256, 256>>>(Wq, Wk, Wv);
    qkv_hmma_kernel<<<(N_NODES + GBM - 1) / GBM, 256>>>(h, bq, bk, bv);

    // Join, then gather: one warp per node, 8 nodes per block.
    cudaStreamWaitEvent(0, sr.join, 0);
    gather_kernel<<<(N_NODES + 7) / 8, 256>>>(out);
}